// round 1
// baseline (speedup 1.0000x reference)
#include <cuda_runtime.h>

// ---------------------------------------------------------------------------
// GraphSAGE fused pipeline, fp32 SIMT baseline.
//   B=16384 roots, fanouts (3,5), D_IN=256, D_HALF=128, D_OUT=128
// ---------------------------------------------------------------------------

#define B_ROOT 16384
#define R1     49152        // B*3
#define R2     245760       // B*15
#define D      256
#define DV     64           // float4 per row
#define H      128

// Scratch (device globals; no allocations allowed).
__device__ float g_A0n[B_ROOT * D];   // mean of emb[neigh1] groups of 3
__device__ float g_A1n[R1 * D];       // mean of emb[neigh2] groups of 5
__device__ float g_F0 [B_ROOT * D];   // layer0 output, pair 0
__device__ float g_F1 [R1 * D];       // layer0 output, pair 1
__device__ float g_M1 [B_ROOT * D];   // mean of F1 groups of 3
__device__ float g_G  [B_ROOT * D];   // layer1 output (normalized in place)

// ---------------------------------------------------------------------------
// Gather + mean over KF consecutive indices:  out[r] = mean_j emb[idx[r*KF+j]]
// one thread per float4 of output
// ---------------------------------------------------------------------------
template <int KF>
__global__ void gather_mean_k(const float4* __restrict__ emb,
                              const int*    __restrict__ idx,
                              float4*       __restrict__ out,
                              int R)
{
    int t = blockIdx.x * blockDim.x + threadIdx.x;
    if (t >= R * DV) return;
    int r = t >> 6;
    int c = t & 63;
    float x = 0.f, y = 0.f, z = 0.f, w = 0.f;
#pragma unroll
    for (int j = 0; j < KF; ++j) {
        int row = idx[r * KF + j];
        float4 v = emb[(size_t)row * DV + c];
        x += v.x; y += v.y; z += v.z; w += v.w;
    }
    const float s = 1.0f / (float)KF;
    out[t] = make_float4(x * s, y * s, z * s, w * s);
}

// ---------------------------------------------------------------------------
// Mean over KF consecutive rows of a dense matrix: out[r] = mean_j in[r*KF+j]
// ---------------------------------------------------------------------------
template <int KF>
__global__ void mean_rows_k(const float4* __restrict__ in,
                            float4*       __restrict__ out,
                            int R)
{
    int t = blockIdx.x * blockDim.x + threadIdx.x;
    if (t >= R * DV) return;
    int r = t >> 6;
    int c = t & 63;
    float x = 0.f, y = 0.f, z = 0.f, w = 0.f;
#pragma unroll
    for (int j = 0; j < KF; ++j) {
        float4 v = in[(size_t)(r * KF + j) * DV + c];
        x += v.x; y += v.y; z += v.z; w += v.w;
    }
    const float s = 1.0f / (float)KF;
    out[t] = make_float4(x * s, y * s, z * s, w * s);
}

// ---------------------------------------------------------------------------
// SGEMM:  C[m, col_off + n] = act( sum_k A[row(m), k] * W[n, k] + bias[n] )
//   A: [*, 256] row-major (optionally indirected through gidx)
//   W: [128, 256] row-major
//   C: row stride ldc
// Tile: BM=128, BN=128 (full N), BK=16; 256 threads, 8x8 per thread.
// ---------------------------------------------------------------------------
__global__ __launch_bounds__(256)
void sgemm_k(const float* __restrict__ A,
             const int*   __restrict__ gidx,     // may be null
             const float* __restrict__ W,
             const float* __restrict__ bias,
             float*       __restrict__ C,
             int ldc, int col_off, int do_relu)
{
    __shared__ float As[16][132];
    __shared__ float Ws[16][132];

    const int tid = threadIdx.x;
    const int tx  = tid & 15;          // 0..15 -> n block of 8
    const int ty  = tid >> 4;          // 0..15 -> m block of 8
    const int m0  = blockIdx.x * 128;

    float acc[8][8];
#pragma unroll
    for (int i = 0; i < 8; ++i)
#pragma unroll
        for (int j = 0; j < 8; ++j) acc[i][j] = 0.f;

    for (int kb = 0; kb < D; kb += 16) {
        // load A tile (128 rows x 16 cols) and W tile (128 rows x 16 cols)
#pragma unroll
        for (int s = 0; s < 2; ++s) {
            int t   = tid + s * 256;           // 0..511
            int row = t >> 2;                  // 0..127
            int c4  = (t & 3) << 2;            // 0,4,8,12

            int arow = m0 + row;
            if (gidx) arow = gidx[arow];
            float4 va = *(const float4*)&A[(size_t)arow * D + kb + c4];
            As[c4 + 0][row] = va.x;
            As[c4 + 1][row] = va.y;
            As[c4 + 2][row] = va.z;
            As[c4 + 3][row] = va.w;

            float4 vw = *(const float4*)&W[(size_t)row * D + kb + c4];
            Ws[c4 + 0][row] = vw.x;
            Ws[c4 + 1][row] = vw.y;
            Ws[c4 + 2][row] = vw.z;
            Ws[c4 + 3][row] = vw.w;
        }
        __syncthreads();

#pragma unroll
        for (int k = 0; k < 16; ++k) {
            float a[8], b[8];
#pragma unroll
            for (int i = 0; i < 8; ++i) a[i] = As[k][ty * 8 + i];
#pragma unroll
            for (int j = 0; j < 8; ++j) b[j] = Ws[k][tx * 8 + j];
#pragma unroll
            for (int i = 0; i < 8; ++i)
#pragma unroll
                for (int j = 0; j < 8; ++j)
                    acc[i][j] = fmaf(a[i], b[j], acc[i][j]);
        }
        __syncthreads();
    }

    // epilogue
#pragma unroll
    for (int i = 0; i < 8; ++i) {
        int m = m0 + ty * 8 + i;
#pragma unroll
        for (int j = 0; j < 8; ++j) {
            int n = tx * 8 + j;
            float v = acc[i][j] + bias[n];
            if (do_relu) v = fmaxf(v, 0.f);
            C[(size_t)m * ldc + col_off + n] = v;
        }
    }
}

// ---------------------------------------------------------------------------
// Row L2 normalize in place (one warp per 256-float row).
// ---------------------------------------------------------------------------
__global__ void norm_rows_k(float4* __restrict__ G, int R)
{
    int r    = blockIdx.x * 8 + (threadIdx.x >> 5);
    int lane = threadIdx.x & 31;
    if (r >= R) return;

    float4 v0 = G[(size_t)r * DV + lane];
    float4 v1 = G[(size_t)r * DV + 32 + lane];
    float ss = v0.x * v0.x + v0.y * v0.y + v0.z * v0.z + v0.w * v0.w
             + v1.x * v1.x + v1.y * v1.y + v1.z * v1.z + v1.w * v1.w;
#pragma unroll
    for (int o = 16; o > 0; o >>= 1)
        ss += __shfl_xor_sync(0xffffffffu, ss, o);

    float s = 1.0f / fmaxf(sqrtf(ss), 1e-12f);
    v0.x *= s; v0.y *= s; v0.z *= s; v0.w *= s;
    v1.x *= s; v1.y *= s; v1.z *= s; v1.w *= s;
    G[(size_t)r * DV + lane]      = v0;
    G[(size_t)r * DV + 32 + lane] = v1;
}

// ---------------------------------------------------------------------------
extern "C" void kernel_launch(void* const* d_in, const int* in_sizes, int n_in,
                              void* d_out, int out_size)
{
    const float* emb      = (const float*)d_in[0];
    const float* w_self0  = (const float*)d_in[1];
    const float* b_self0  = (const float*)d_in[2];
    const float* w_neigh0 = (const float*)d_in[3];
    const float* b_neigh0 = (const float*)d_in[4];
    const float* w_self1  = (const float*)d_in[5];
    const float* b_self1  = (const float*)d_in[6];
    const float* w_neigh1 = (const float*)d_in[7];
    const float* b_neigh1 = (const float*)d_in[8];
    const float* fc_w     = (const float*)d_in[9];
    const float* fc_b     = (const float*)d_in[10];
    const int*   nodeids  = (const int*)d_in[11];
    const int*   neigh1   = (const int*)d_in[12];
    const int*   neigh2   = (const int*)d_in[13];
    float*       out      = (float*)d_out;

    float *A0n, *A1n, *F0, *F1, *M1, *G;
    cudaGetSymbolAddress((void**)&A0n, g_A0n);
    cudaGetSymbolAddress((void**)&A1n, g_A1n);
    cudaGetSymbolAddress((void**)&F0,  g_F0);
    cudaGetSymbolAddress((void**)&F1,  g_F1);
    cudaGetSymbolAddress((void**)&M1,  g_M1);
    cudaGetSymbolAddress((void**)&G,   g_G);

    const int TPB = 256;

    // 1) neighbor means (layer-0 inputs)
    gather_mean_k<3><<<(B_ROOT * DV + TPB - 1) / TPB, TPB>>>(
        (const float4*)emb, neigh1, (float4*)A0n, B_ROOT);
    gather_mean_k<5><<<(R1 * DV + TPB - 1) / TPB, TPB>>>(
        (const float4*)emb, neigh2, (float4*)A1n, R1);

    // 2) layer 0: F0 = relu([emb[nodeids]@Ws0^T+bs0 | A0n@Wn0^T+bn0])
    sgemm_k<<<B_ROOT / 128, 256>>>(emb, nodeids, w_self0, b_self0, F0, D, 0, 1);
    sgemm_k<<<B_ROOT / 128, 256>>>(A0n, nullptr, w_neigh0, b_neigh0, F0, D, H, 1);

    //    F1 = relu([emb[neigh1]@Ws0^T+bs0 | A1n@Wn0^T+bn0])
    sgemm_k<<<R1 / 128, 256>>>(emb, neigh1, w_self0, b_self0, F1, D, 0, 1);
    sgemm_k<<<R1 / 128, 256>>>(A1n, nullptr, w_neigh0, b_neigh0, F1, D, H, 1);

    // 3) layer 1: M1 = mean of F1 groups of 3
    mean_rows_k<3><<<(B_ROOT * DV + TPB - 1) / TPB, TPB>>>(
        (const float4*)F1, (float4*)M1, B_ROOT);

    sgemm_k<<<B_ROOT / 128, 256>>>(F0, nullptr, w_self1, b_self1, G, D, 0, 1);
    sgemm_k<<<B_ROOT / 128, 256>>>(M1, nullptr, w_neigh1, b_neigh1, G, D, H, 1);

    // 4) row-normalize, then FC
    norm_rows_k<<<B_ROOT / 8, 256>>>((float4*)G, B_ROOT);
    sgemm_k<<<B_ROOT / 128, 256>>>(G, nullptr, fc_w, fc_b, out, H, 0, 0);
}

// round 3
// speedup vs baseline: 2.2694x; 2.2694x over previous
#include <cuda_runtime.h>
#include <cuda_bf16.h>
#include <cstdint>

// ---------------------------------------------------------------------------
// GraphSAGE via mma.sync bf16 (hi/lo split, 3-product fp32-accurate).
//   MODE 0: F0 = relu([emb[nodeids]@Ws0' | mean3(emb[neigh1])@Wn0'])
//   MODE 1: F1 = relu([emb[neigh1] @Ws0' | mean5(emb[neigh2])@Wn0'])
//   MODE 2: h  = relu([F0@Ws1' | mean3(F1)@Wn1']); h/=||h||2; out = h@fc' + b
// CTA: 512 thr (16 warps), tile M=128 x N=256 (self|neigh), K chunked by 64.
// ---------------------------------------------------------------------------

#define B_ROOT 16384
#define R1     49152
#define RS1    72          // stage-1 tile row stride (bf16 elems), padded
#define RSH    264         // stage-2 h row stride (256 + 8 pad)

// SMEM byte offsets (stage-2 regions reuse stage-1 space after sync)
#define SA_SH  0           // self A hi   [128][72]
#define SA_SL  18432       // self A lo
#define SA_NH  36864       // neigh A hi
#define SA_NL  55296       // neigh A lo
#define SW_H   73728       // W hi [256][72]  (rows 0..127 self, 128..255 neigh)
#define SW_L   110592      // W lo
#define SH_H   0           // MODE2 stage2: h hi [128][264]
#define SH_L   67584       // h lo
#define SFC_H  135168      // fc hi [128][72]
#define SFC_L  153600      // fc lo
#define SS_OFF 172032      // float ss[128]
#define SMEM_M01 147456
#define SMEM_M2  (172032 + 512)

// ---------------- scratch ----------------------------------------------------
__device__ __nv_bfloat16 g_whi[5 * 32768];
__device__ __nv_bfloat16 g_wlo[5 * 32768];
__device__ float g_F0[B_ROOT * 256];
__device__ float g_F1[R1 * 256];

// ---------------- helpers ----------------------------------------------------
__device__ __forceinline__ void split2(float a, float b, uint32_t& h, uint32_t& l) {
    __nv_bfloat16 ah = __float2bfloat16_rn(a), bh = __float2bfloat16_rn(b);
    __nv_bfloat16 al = __float2bfloat16_rn(a - __bfloat162float(ah));
    __nv_bfloat16 bl = __float2bfloat16_rn(b - __bfloat162float(bh));
    __nv_bfloat162 ph = __halves2bfloat162(ah, bh);
    __nv_bfloat162 pl = __halves2bfloat162(al, bl);
    h = *reinterpret_cast<uint32_t*>(&ph);
    l = *reinterpret_cast<uint32_t*>(&pl);
}

__device__ __forceinline__ void split8(const float* v, uint4& h4, uint4& l4) {
    uint32_t h[4], l[4];
#pragma unroll
    for (int i = 0; i < 4; ++i) split2(v[2 * i], v[2 * i + 1], h[i], l[i]);
    h4 = make_uint4(h[0], h[1], h[2], h[3]);
    l4 = make_uint4(l[0], l[1], l[2], l[3]);
}

// D += A x B   (m16n8k16, row.col, bf16 -> f32)
__device__ __forceinline__ void mma16816(float* d, const uint32_t* a,
                                         uint32_t b0, uint32_t b1) {
    asm volatile(
        "mma.sync.aligned.m16n8k16.row.col.f32.bf16.bf16.f32 "
        "{%0,%1,%2,%3}, {%4,%5,%6,%7}, {%8,%9}, {%0,%1,%2,%3};"
        : "+f"(d[0]), "+f"(d[1]), "+f"(d[2]), "+f"(d[3])
        : "r"(a[0]), "r"(a[1]), "r"(a[2]), "r"(a[3]), "r"(b0), "r"(b1));
}

// ---------------- weight pre-split --------------------------------------------
__global__ void conv_w(const float* __restrict__ a, const float* __restrict__ b,
                       const float* __restrict__ c, const float* __restrict__ d,
                       const float* __restrict__ e,
                       __nv_bfloat16* __restrict__ hi, __nv_bfloat16* __restrict__ lo) {
    int t = blockIdx.x * blockDim.x + threadIdx.x;   // 5*32768 total
    const float* src[5] = {a, b, c, d, e};
    float x = src[t >> 15][t & 32767];
    __nv_bfloat16 h = __float2bfloat16_rn(x);
    hi[t] = h;
    lo[t] = __float2bfloat16_rn(x - __bfloat162float(h));
}

// ---------------- fused agg kernel --------------------------------------------
template <int MODE>
__global__ void __launch_bounds__(512, 1)
agg_kernel(const float* __restrict__ srcS, const float* __restrict__ srcN,
           const int* __restrict__ idxS, const int* __restrict__ idxN,
           const __nv_bfloat16* __restrict__ wS_hi, const __nv_bfloat16* __restrict__ wS_lo,
           const __nv_bfloat16* __restrict__ wN_hi, const __nv_bfloat16* __restrict__ wN_lo,
           const float* __restrict__ bS, const float* __restrict__ bN,
           float* __restrict__ outF,
           const __nv_bfloat16* __restrict__ fc_hi, const __nv_bfloat16* __restrict__ fc_lo,
           const float* __restrict__ fcb, float* __restrict__ out2)
{
    constexpr int KF = (MODE == 1) ? 5 : 3;
    extern __shared__ char smem[];

    const int tid = threadIdx.x, lane = tid & 31, wid = tid >> 5;
    const int wm = wid & 1;        // warp row   (0..1)  -> 64 rows
    const int wn = wid >> 1;       // warp col   (0..7)  -> 32 cols
    const int lr = lane >> 2;      // 0..7
    const int lc = (lane & 3) * 2; // 0,2,4,6
    const int m0 = blockIdx.x * 128;

    // loader indices
    const int r  = tid >> 2;            // 0..127
    const int cq = (tid & 3) * 16;      // 0,16,32,48
    const int wr = tid >> 1;            // 0..255
    const int wc = (tid & 1) * 32;      // 0,32

    int rowS = (MODE == 2) ? (m0 + r) : idxS[m0 + r];
    int rowN[KF];
#pragma unroll
    for (int j = 0; j < KF; ++j)
        rowN[j] = (MODE == 2) ? ((m0 + r) * 3 + j)
                              : idxN[(size_t)(m0 + r) * KF + j];

    float d[4][4][4];
#pragma unroll
    for (int i = 0; i < 4; ++i)
#pragma unroll
        for (int j = 0; j < 4; ++j)
#pragma unroll
            for (int k = 0; k < 4; ++k) d[i][j][k] = 0.f;

    // ================= stage 1: K = 256 in 4 chunks of 64 =====================
    for (int ch = 0; ch < 4; ++ch) {
        const int kb = ch * 64;
        { // A self: gather + split
            const float* p = srcS + (size_t)rowS * 256 + kb + cq;
            float v[16];
#pragma unroll
            for (int q = 0; q < 4; ++q) {
                float4 f = __ldg((const float4*)(p + q * 4));
                v[q * 4 + 0] = f.x; v[q * 4 + 1] = f.y;
                v[q * 4 + 2] = f.z; v[q * 4 + 3] = f.w;
            }
            uint4 h0, l0, h1, l1;
            split8(v, h0, l0); split8(v + 8, h1, l1);
            const size_t off = (size_t)(r * RS1 + cq) * 2;
            *(uint4*)(smem + SA_SH + off)      = h0;
            *(uint4*)(smem + SA_SH + off + 16) = h1;
            *(uint4*)(smem + SA_SL + off)      = l0;
            *(uint4*)(smem + SA_SL + off + 16) = l1;
        }
        { // A neigh: gather + mean + split
            float acc[16];
#pragma unroll
            for (int i = 0; i < 16; ++i) acc[i] = 0.f;
#pragma unroll
            for (int j = 0; j < KF; ++j) {
                const float* p = srcN + (size_t)rowN[j] * 256 + kb + cq;
#pragma unroll
                for (int q = 0; q < 4; ++q) {
                    float4 f = __ldg((const float4*)(p + q * 4));
                    acc[q * 4 + 0] += f.x; acc[q * 4 + 1] += f.y;
                    acc[q * 4 + 2] += f.z; acc[q * 4 + 3] += f.w;
                }
            }
            const float s = 1.0f / (float)KF;
#pragma unroll
            for (int i = 0; i < 16; ++i) acc[i] *= s;
            uint4 h0, l0, h1, l1;
            split8(acc, h0, l0); split8(acc + 8, h1, l1);
            const size_t off = (size_t)(r * RS1 + cq) * 2;
            *(uint4*)(smem + SA_NH + off)      = h0;
            *(uint4*)(smem + SA_NH + off + 16) = h1;
            *(uint4*)(smem + SA_NL + off)      = l0;
            *(uint4*)(smem + SA_NL + off + 16) = l1;
        }
        { // W tiles (pre-split bf16): rows 0..127 self, 128..255 neigh
            const __nv_bfloat16* sh = (wr < 128)
                ? wS_hi + (size_t)wr * 256 : wN_hi + (size_t)(wr - 128) * 256;
            const __nv_bfloat16* sl = (wr < 128)
                ? wS_lo + (size_t)wr * 256 : wN_lo + (size_t)(wr - 128) * 256;
            const size_t off = (size_t)(wr * RS1 + wc) * 2;
#pragma unroll
            for (int q = 0; q < 4; ++q) {
                *(uint4*)(smem + SW_H + off + q * 16) =
                    __ldg((const uint4*)(sh + kb + wc) + q);
                *(uint4*)(smem + SW_L + off + q * 16) =
                    __ldg((const uint4*)(sl + kb + wc) + q);
            }
        }
        __syncthreads();

        const char* Ah = smem + (wn < 4 ? SA_SH : SA_NH);
        const char* Al = smem + (wn < 4 ? SA_SL : SA_NL);
#pragma unroll
        for (int ks = 0; ks < 4; ++ks) {
            const int kk = ks * 16;
            uint32_t ah[4][4], al[4][4];
#pragma unroll
            for (int mi = 0; mi < 4; ++mi) {
                const int e0 = (wm * 64 + mi * 16 + lr) * RS1 + kk + lc;
                ah[mi][0] = *(const uint32_t*)(Ah + (size_t)e0 * 2);
                ah[mi][1] = *(const uint32_t*)(Ah + (size_t)(e0 + 8 * RS1) * 2);
                ah[mi][2] = *(const uint32_t*)(Ah + (size_t)(e0 + 8) * 2);
                ah[mi][3] = *(const uint32_t*)(Ah + (size_t)(e0 + 8 * RS1 + 8) * 2);
                al[mi][0] = *(const uint32_t*)(Al + (size_t)e0 * 2);
                al[mi][1] = *(const uint32_t*)(Al + (size_t)(e0 + 8 * RS1) * 2);
                al[mi][2] = *(const uint32_t*)(Al + (size_t)(e0 + 8) * 2);
                al[mi][3] = *(const uint32_t*)(Al + (size_t)(e0 + 8 * RS1 + 8) * 2);
            }
#pragma unroll
            for (int ni = 0; ni < 4; ++ni) {
                const int e = (wn * 32 + ni * 8 + lr) * RS1 + kk + lc;
                const uint32_t bh0 = *(const uint32_t*)(smem + SW_H + (size_t)e * 2);
                const uint32_t bh1 = *(const uint32_t*)(smem + SW_H + (size_t)(e + 8) * 2);
                const uint32_t bl0 = *(const uint32_t*)(smem + SW_L + (size_t)e * 2);
                const uint32_t bl1 = *(const uint32_t*)(smem + SW_L + (size_t)(e + 8) * 2);
#pragma unroll
                for (int mi = 0; mi < 4; ++mi) {
                    mma16816(d[mi][ni], ah[mi], bh0, bh1);
                    mma16816(d[mi][ni], ah[mi], bl0, bl1);
                    mma16816(d[mi][ni], al[mi], bh0, bh1);
                }
            }
        }
        __syncthreads();
    }

    if (MODE != 2) {
        // ---- epilogue: bias + relu -> outF fp32 [*, 256] ----------------------
#pragma unroll
        for (int mi = 0; mi < 4; ++mi) {
            const int row = m0 + wm * 64 + mi * 16 + lr;
#pragma unroll
            for (int ni = 0; ni < 4; ++ni) {
                const int col = wn * 32 + ni * 8 + lc;
                const float b0 = (col < 128) ? bS[col] : bN[col - 128];
                const float b1 = (col + 1 < 128) ? bS[col + 1] : bN[col - 127];
                float2 v0 = make_float2(fmaxf(d[mi][ni][0] + b0, 0.f),
                                        fmaxf(d[mi][ni][1] + b1, 0.f));
                float2 v1 = make_float2(fmaxf(d[mi][ni][2] + b0, 0.f),
                                        fmaxf(d[mi][ni][3] + b1, 0.f));
                *(float2*)&outF[(size_t)row * 256 + col]       = v0;
                *(float2*)&outF[(size_t)(row + 8) * 256 + col] = v1;
            }
        }
        return;
    }

    // ================= MODE 2: bias+relu, L2-norm, FC ==========================
    float* ss = (float*)(smem + SS_OFF);
    if (tid < 128) ss[tid] = 0.f;
    __syncthreads();

#pragma unroll
    for (int mi = 0; mi < 4; ++mi) {
        const int r0 = wm * 64 + mi * 16 + lr;
        float s0 = 0.f, s1 = 0.f;
#pragma unroll
        for (int ni = 0; ni < 4; ++ni) {
            const int col = wn * 32 + ni * 8 + lc;
            const float b0 = (col < 128) ? bS[col] : bN[col - 128];
            const float b1 = (col + 1 < 128) ? bS[col + 1] : bN[col - 127];
            d[mi][ni][0] = fmaxf(d[mi][ni][0] + b0, 0.f);
            d[mi][ni][1] = fmaxf(d[mi][ni][1] + b1, 0.f);
            d[mi][ni][2] = fmaxf(d[mi][ni][2] + b0, 0.f);
            d[mi][ni][3] = fmaxf(d[mi][ni][3] + b1, 0.f);
            s0 += d[mi][ni][0] * d[mi][ni][0] + d[mi][ni][1] * d[mi][ni][1];
            s1 += d[mi][ni][2] * d[mi][ni][2] + d[mi][ni][3] * d[mi][ni][3];
        }
        s0 += __shfl_xor_sync(0xffffffffu, s0, 1);
        s0 += __shfl_xor_sync(0xffffffffu, s0, 2);
        s1 += __shfl_xor_sync(0xffffffffu, s1, 1);
        s1 += __shfl_xor_sync(0xffffffffu, s1, 2);
        if ((lane & 3) == 0) {
            atomicAdd(&ss[r0], s0);
            atomicAdd(&ss[r0 + 8], s1);
        }
    }
    __syncthreads();

    // scale rows, split h -> SMEM (reusing stage-1 region)
#pragma unroll
    for (int mi = 0; mi < 4; ++mi) {
        const int r0 = wm * 64 + mi * 16 + lr;
        const float sc0 = 1.0f / fmaxf(sqrtf(ss[r0]), 1e-12f);
        const float sc1 = 1.0f / fmaxf(sqrtf(ss[r0 + 8]), 1e-12f);
#pragma unroll
        for (int ni = 0; ni < 4; ++ni) {
            const int col = wn * 32 + ni * 8 + lc;
            uint32_t h0, l0, h1, l1;
            split2(d[mi][ni][0] * sc0, d[mi][ni][1] * sc0, h0, l0);
            split2(d[mi][ni][2] * sc1, d[mi][ni][3] * sc1, h1, l1);
            const size_t o0 = (size_t)(r0 * RSH + col) * 2;
            const size_t o1 = (size_t)((r0 + 8) * RSH + col) * 2;
            *(uint32_t*)(smem + SH_H + o0) = h0;
            *(uint32_t*)(smem + SH_L + o0) = l0;
            *(uint32_t*)(smem + SH_H + o1) = h1;
            *(uint32_t*)(smem + SH_L + o1) = l1;
        }
    }
    __syncthreads();

    // stage 2: out = h @ fc^T   (M=128, N=128, K=256 in 4 chunks)
    float e2[4][2][4];
#pragma unroll
    for (int i = 0; i < 4; ++i)
#pragma unroll
        for (int j = 0; j < 2; ++j)
#pragma unroll
            for (int k = 0; k < 4; ++k) e2[i][j][k] = 0.f;

    for (int ch = 0; ch < 4; ++ch) {
        const int kb = ch * 64;
        { // fc chunk tiles hi/lo
            const size_t off = (size_t)(r * RS1 + cq) * 2;
            const uint4* gh = (const uint4*)(fc_hi + (size_t)r * 256 + kb + cq);
            const uint4* gl = (const uint4*)(fc_lo + (size_t)r * 256 + kb + cq);
            *(uint4*)(smem + SFC_H + off)      = __ldg(gh);
            *(uint4*)(smem + SFC_H + off + 16) = __ldg(gh + 1);
            *(uint4*)(smem + SFC_L + off)      = __ldg(gl);
            *(uint4*)(smem + SFC_L + off + 16) = __ldg(gl + 1);
        }
        __syncthreads();

#pragma unroll
        for (int ks = 0; ks < 4; ++ks) {
            const int kkg = kb + ks * 16;     // global k into h
            const int kkl = ks * 16;          // local k into fc tile
            uint32_t ah[4][4], al[4][4];
#pragma unroll
            for (int mi = 0; mi < 4; ++mi) {
                const int e0 = (wm * 64 + mi * 16 + lr) * RSH + kkg + lc;
                ah[mi][0] = *(const uint32_t*)(smem + SH_H + (size_t)e0 * 2);
                ah[mi][1] = *(const uint32_t*)(smem + SH_H + (size_t)(e0 + 8 * RSH) * 2);
                ah[mi][2] = *(const uint32_t*)(smem + SH_H + (size_t)(e0 + 8) * 2);
                ah[mi][3] = *(const uint32_t*)(smem + SH_H + (size_t)(e0 + 8 * RSH + 8) * 2);
                al[mi][0] = *(const uint32_t*)(smem + SH_L + (size_t)e0 * 2);
                al[mi][1] = *(const uint32_t*)(smem + SH_L + (size_t)(e0 + 8 * RSH) * 2);
                al[mi][2] = *(const uint32_t*)(smem + SH_L + (size_t)(e0 + 8) * 2);
                al[mi][3] = *(const uint32_t*)(smem + SH_L + (size_t)(e0 + 8 * RSH + 8) * 2);
            }
#pragma unroll
            for (int ni = 0; ni < 2; ++ni) {
                const int e0 = (wn * 16 + ni * 8 + lr) * RS1 + kkl + lc;
                const uint32_t bh0 = *(const uint32_t*)(smem + SFC_H + (size_t)e0 * 2);
                const uint32_t bh1 = *(const uint32_t*)(smem + SFC_H + (size_t)(e0 + 8) * 2);
                const uint32_t bl0 = *(const uint32_t*)(smem + SFC_L + (size_t)e0 * 2);
                const uint32_t bl1 = *(const uint32_t*)(smem + SFC_L + (size_t)(e0 + 8) * 2);
#pragma unroll
                for (int mi = 0; mi < 4; ++mi) {
                    mma16816(e2[mi][ni], ah[mi], bh0, bh1);
                    mma16816(e2[mi][ni], ah[mi], bl0, bl1);
                    mma16816(e2[mi][ni], al[mi], bh0, bh1);
                }
            }
        }
        __syncthreads();
    }

    // final write: + fc_b -> out2 [*, 128]
#pragma unroll
    for (int mi = 0; mi < 4; ++mi) {
        const int row = m0 + wm * 64 + mi * 16 + lr;
#pragma unroll
        for (int ni = 0; ni < 2; ++ni) {
            const int col = wn * 16 + ni * 8 + lc;
            float2 v0 = make_float2(e2[mi][ni][0] + fcb[col],
                                    e2[mi][ni][1] + fcb[col + 1]);
            float2 v1 = make_float2(e2[mi][ni][2] + fcb[col],
                                    e2[mi][ni][3] + fcb[col + 1]);
            *(float2*)&out2[(size_t)row * 128 + col]       = v0;
            *(float2*)&out2[(size_t)(row + 8) * 128 + col] = v1;
        }
    }
}

// ---------------------------------------------------------------------------
extern "C" void kernel_launch(void* const* d_in, const int* in_sizes, int n_in,
                              void* d_out, int out_size)
{
    const float* emb      = (const float*)d_in[0];
    const float* w_self0  = (const float*)d_in[1];
    const float* b_self0  = (const float*)d_in[2];
    const float* w_neigh0 = (const float*)d_in[3];
    const float* b_neigh0 = (const float*)d_in[4];
    const float* w_self1  = (const float*)d_in[5];
    const float* b_self1  = (const float*)d_in[6];
    const float* w_neigh1 = (const float*)d_in[7];
    const float* b_neigh1 = (const float*)d_in[8];
    const float* fc_w     = (const float*)d_in[9];
    const float* fc_b     = (const float*)d_in[10];
    const int*   nodeids  = (const int*)d_in[11];
    const int*   neigh1   = (const int*)d_in[12];
    const int*   neigh2   = (const int*)d_in[13];
    float*       out      = (float*)d_out;

    __nv_bfloat16 *WHI, *WLO;
    float *F0, *F1;
    cudaGetSymbolAddress((void**)&WHI, g_whi);
    cudaGetSymbolAddress((void**)&WLO, g_wlo);
    cudaGetSymbolAddress((void**)&F0, g_F0);
    cudaGetSymbolAddress((void**)&F1, g_F1);

    cudaFuncSetAttribute(agg_kernel<0>, cudaFuncAttributeMaxDynamicSharedMemorySize, SMEM_M01);
    cudaFuncSetAttribute(agg_kernel<1>, cudaFuncAttributeMaxDynamicSharedMemorySize, SMEM_M01);
    cudaFuncSetAttribute(agg_kernel<2>, cudaFuncAttributeMaxDynamicSharedMemorySize, SMEM_M2);

    // pre-split all weights to bf16 hi/lo
    conv_w<<<640, 256>>>(w_self0, w_neigh0, w_self1, w_neigh1, fc_w, WHI, WLO);

    // layer0 F0: self = emb[nodeids], neigh = mean3 emb[neigh1]
    agg_kernel<0><<<B_ROOT / 128, 512, SMEM_M01>>>(
        emb, emb, nodeids, neigh1,
        WHI, WLO, WHI + 32768, WLO + 32768,
        b_self0, b_neigh0, F0, nullptr, nullptr, nullptr, nullptr);

    // layer0 F1: self = emb[neigh1], neigh = mean5 emb[neigh2]
    agg_kernel<1><<<R1 / 128, 512, SMEM_M01>>>(
        emb, emb, neigh1, neigh2,
        WHI, WLO, WHI + 32768, WLO + 32768,
        b_self0, b_neigh0, F1, nullptr, nullptr, nullptr, nullptr);

    // layer1 + norm + FC fused
    agg_kernel<2><<<B_ROOT / 128, 512, SMEM_M2>>>(
        F0, F1, nullptr, nullptr,
        WHI + 65536, WLO + 65536, WHI + 98304, WLO + 98304,
        b_self1, b_neigh1, nullptr,
        WHI + 131072, WLO + 131072, fc_b, out);
}